// round 6
// baseline (speedup 1.0000x reference)
#include <cuda_runtime.h>
#include <cstdint>

// MaxPoolAggregator: out[q, :] = max_{s<10} features[nbrs[q,s], :]
// features: [1'000'000, 128] f32, nbrs: [100'000, 10] i32, out: [100'000, 128] f32
//
// R5: 256-bit gathers (LDG.E.256). One warp per query; each half-warp covers
// one full 512B row (16 lanes x 32B), so one warp-level v8 load fetches TWO
// sampled rows. 10 samples = 5 load instructions/warp (was 10 float4 loads).
// Halves LSU issue + L1tex queue pressure per byte. Reduce: local max over
// 5 pairs, then shfl.xor(16) to combine the two halves, coalesced 512B store.

#define NUM_SAMPLE 10
#define D_FEAT 128
#define ROW_BYTES (D_FEAT * 4)   // 512
#define NPAIR (NUM_SAMPLE / 2)   // 5

__device__ __forceinline__ void ldg256_evict_last(const void* p, float* v) {
    asm volatile(
        "ld.global.nc.L2::evict_last.v8.b32 {%0,%1,%2,%3,%4,%5,%6,%7}, [%8];"
        : "=f"(v[0]), "=f"(v[1]), "=f"(v[2]), "=f"(v[3]),
          "=f"(v[4]), "=f"(v[5]), "=f"(v[6]), "=f"(v[7])
        : "l"(p));
}

__device__ __forceinline__ void stg_streaming16(void* p, float a, float b, float c, float d) {
    asm volatile("st.global.cs.v4.f32 [%0], {%1,%2,%3,%4};"
                 :: "l"(p), "f"(a), "f"(b), "f"(c), "f"(d)
                 : "memory");
}

__global__ __launch_bounds__(128) void maxpool_agg_kernel(
    const char* __restrict__ features,   // [N_NODES, 512B rows]
    const int* __restrict__ nbrs,        // [Q, 10]
    char* __restrict__ out,              // [Q, 512B rows]
    int num_query)
{
    const int warp_global = (blockIdx.x * blockDim.x + threadIdx.x) >> 5;
    const int lane = threadIdx.x & 31;
    if (warp_global >= num_query) return;

    const int half = lane >> 4;      // 0: row 2p, 1: row 2p+1
    const int sub  = lane & 15;      // 32B chunk within the row

    const int* nb = nbrs + (size_t)warp_global * NUM_SAMPLE;

    // Issue all 5 x 256-bit gathers up front (10 rows total, max MLP).
    float v[NPAIR][8];
#pragma unroll
    for (int p = 0; p < NPAIR; ++p) {
        const int id = __ldg(nb + 2 * p + half);           // uniform per half-warp
        const char* src = features + (size_t)id * ROW_BYTES + sub * 32;
        ldg256_evict_last(src, v[p]);
    }

    // Local max over this half-warp's 5 rows.
    float m[8];
#pragma unroll
    for (int j = 0; j < 8; ++j) m[j] = v[0][j];
#pragma unroll
    for (int p = 1; p < NPAIR; ++p)
#pragma unroll
        for (int j = 0; j < 8; ++j) m[j] = fmaxf(m[j], v[p][j]);

    // Combine the two halves: lane l and lane l^16 hold the same dims
    // (same sub) for disjoint sample sets.
#pragma unroll
    for (int j = 0; j < 8; ++j)
        m[j] = fmaxf(m[j], __shfl_xor_sync(0xffffffffu, m[j], 16));

    // Coalesced 512B store: each lane writes 16B. half 0 -> first 16B of its
    // 32B chunk (m[0..3]), half 1 -> second 16B (m[4..7]).
    char* dst = out + (size_t)warp_global * ROW_BYTES + sub * 32 + half * 16;
    if (half == 0) stg_streaming16(dst, m[0], m[1], m[2], m[3]);
    else           stg_streaming16(dst, m[4], m[5], m[6], m[7]);
}

extern "C" void kernel_launch(void* const* d_in, const int* in_sizes, int n_in,
                              void* d_out, int out_size)
{
    const char* features = (const char*)d_in[0];
    const int*  nbrs     = (const int*)d_in[1];
    // d_in[2] is num_sample (device scalar) — shape is static, hardcoded to 10.

    const int num_query = in_sizes[1] / NUM_SAMPLE;   // 100'000

    const int warps_per_block = 4;                    // 128 threads
    const int threads = warps_per_block * 32;
    const int blocks = (num_query + warps_per_block - 1) / warps_per_block;

    maxpool_agg_kernel<<<blocks, threads>>>(features, nbrs, (char*)d_out, num_query);
}

// round 7
// speedup vs baseline: 1.0236x; 1.0236x over previous
#include <cuda_runtime.h>
#include <cstdint>

// MaxPoolAggregator: out[q, :] = max_{s<10} features[nbrs[q,s], :]
// features: [1'000'000, 128] f32, nbrs: [100'000, 10] i32, out: [100'000, 128] f32
//
// R5: 256-bit gathers (LDG.E.256). One warp per query; each half-warp covers
// one full 512B row (16 lanes x 32B), so one warp-level v8 load fetches TWO
// sampled rows. 10 samples = 5 load instructions/warp (was 10 float4 loads).
// Halves LSU issue + L1tex queue pressure per byte. Reduce: local max over
// 5 pairs, then shfl.xor(16) to combine the two halves, coalesced 512B store.

#define NUM_SAMPLE 10
#define D_FEAT 128
#define ROW_BYTES (D_FEAT * 4)   // 512
#define NPAIR (NUM_SAMPLE / 2)   // 5

__device__ __forceinline__ void ldg256_evict_last(const void* p, float* v) {
    asm volatile(
        "ld.global.nc.L2::evict_last.v8.b32 {%0,%1,%2,%3,%4,%5,%6,%7}, [%8];"
        : "=f"(v[0]), "=f"(v[1]), "=f"(v[2]), "=f"(v[3]),
          "=f"(v[4]), "=f"(v[5]), "=f"(v[6]), "=f"(v[7])
        : "l"(p));
}

__device__ __forceinline__ void stg_streaming16(void* p, float a, float b, float c, float d) {
    asm volatile("st.global.cs.v4.f32 [%0], {%1,%2,%3,%4};"
                 :: "l"(p), "f"(a), "f"(b), "f"(c), "f"(d)
                 : "memory");
}

__global__ __launch_bounds__(128) void maxpool_agg_kernel(
    const char* __restrict__ features,   // [N_NODES, 512B rows]
    const int* __restrict__ nbrs,        // [Q, 10]
    char* __restrict__ out,              // [Q, 512B rows]
    int num_query)
{
    const int warp_global = (blockIdx.x * blockDim.x + threadIdx.x) >> 5;
    const int lane = threadIdx.x & 31;
    if (warp_global >= num_query) return;

    const int half = lane >> 4;      // 0: row 2p, 1: row 2p+1
    const int sub  = lane & 15;      // 32B chunk within the row

    const int* nb = nbrs + (size_t)warp_global * NUM_SAMPLE;

    // Issue all 5 x 256-bit gathers up front (10 rows total, max MLP).
    float v[NPAIR][8];
#pragma unroll
    for (int p = 0; p < NPAIR; ++p) {
        const int id = __ldg(nb + 2 * p + half);           // uniform per half-warp
        const char* src = features + (size_t)id * ROW_BYTES + sub * 32;
        ldg256_evict_last(src, v[p]);
    }

    // Local max over this half-warp's 5 rows.
    float m[8];
#pragma unroll
    for (int j = 0; j < 8; ++j) m[j] = v[0][j];
#pragma unroll
    for (int p = 1; p < NPAIR; ++p)
#pragma unroll
        for (int j = 0; j < 8; ++j) m[j] = fmaxf(m[j], v[p][j]);

    // Combine the two halves: lane l and lane l^16 hold the same dims
    // (same sub) for disjoint sample sets.
#pragma unroll
    for (int j = 0; j < 8; ++j)
        m[j] = fmaxf(m[j], __shfl_xor_sync(0xffffffffu, m[j], 16));

    // Coalesced 512B store: each lane writes 16B. half 0 -> first 16B of its
    // 32B chunk (m[0..3]), half 1 -> second 16B (m[4..7]).
    char* dst = out + (size_t)warp_global * ROW_BYTES + sub * 32 + half * 16;
    if (half == 0) stg_streaming16(dst, m[0], m[1], m[2], m[3]);
    else           stg_streaming16(dst, m[4], m[5], m[6], m[7]);
}

extern "C" void kernel_launch(void* const* d_in, const int* in_sizes, int n_in,
                              void* d_out, int out_size)
{
    const char* features = (const char*)d_in[0];
    const int*  nbrs     = (const int*)d_in[1];
    // d_in[2] is num_sample (device scalar) — shape is static, hardcoded to 10.

    const int num_query = in_sizes[1] / NUM_SAMPLE;   // 100'000

    const int warps_per_block = 4;                    // 128 threads
    const int threads = warps_per_block * 32;
    const int blocks = (num_query + warps_per_block - 1) / warps_per_block;

    maxpool_agg_kernel<<<blocks, threads>>>(features, nbrs, (char*)d_out, num_query);
}

// round 8
// speedup vs baseline: 1.0332x; 1.0094x over previous
#include <cuda_runtime.h>
#include <cstdint>

// MaxPoolAggregator: out[q, :] = max_{s<10} features[nbrs[q,s], :]
// features: [1'000'000, 128] f32, nbrs: [100'000, 10] i32, out: [100'000, 128] f32
//
// R8: one query per HALF-warp (2 queries/warp). 10 x 256-bit gathers per warp
// front-batched (each fetches two 512B rows, one per query). launch_bounds
// (128, 4) grants up to 128 regs so ptxas can hold all 10 loads in flight
// (R7 showed ptxas clamped to 32 regs -> MLP ~3). No cross-half shuffle needed;
// each half-warp reduces and stores its own row with streaming v4 stores.

#define NUM_SAMPLE 10
#define D_FEAT 128
#define ROW_BYTES (D_FEAT * 4)   // 512

__device__ __forceinline__ void ldg256_evict_last(const void* p, float* v) {
    asm("ld.global.nc.L2::evict_last.v8.b32 {%0,%1,%2,%3,%4,%5,%6,%7}, [%8];"
        : "=f"(v[0]), "=f"(v[1]), "=f"(v[2]), "=f"(v[3]),
          "=f"(v[4]), "=f"(v[5]), "=f"(v[6]), "=f"(v[7])
        : "l"(p));
}

__device__ __forceinline__ void stg_streaming16(void* p, float a, float b, float c, float d) {
    asm volatile("st.global.cs.v4.f32 [%0], {%1,%2,%3,%4};"
                 :: "l"(p), "f"(a), "f"(b), "f"(c), "f"(d)
                 : "memory");
}

__global__ __launch_bounds__(128, 4) void maxpool_agg_kernel(
    const char* __restrict__ features,   // [N_NODES, 512B rows]
    const int* __restrict__ nbrs,        // [Q, 10]
    char* __restrict__ out,              // [Q, 512B rows]
    int num_query)
{
    const int warp_global = (blockIdx.x * blockDim.x + threadIdx.x) >> 5;
    const int lane = threadIdx.x & 31;
    const int half = lane >> 4;      // which query this half-warp owns
    const int sub  = lane & 15;      // 32B chunk within the 512B row

    const int q = 2 * warp_global + half;
    if (2 * warp_global >= num_query) return;      // whole warp out of range
    const bool active = (q < num_query);
    const int qc = active ? q : 0;                  // safe ids for inactive half

    const int* nb = nbrs + (size_t)qc * NUM_SAMPLE;

    // Load all 10 ids (uniform within the half-warp, L1-broadcast).
    int ids[NUM_SAMPLE];
#pragma unroll
    for (int s = 0; s < NUM_SAMPLE; ++s) ids[s] = __ldg(nb + s);

    // Front-batch all 10 x 256-bit gathers: 10 KB in flight per warp.
    float v[NUM_SAMPLE][8];
#pragma unroll
    for (int s = 0; s < NUM_SAMPLE; ++s) {
        ldg256_evict_last(features + (size_t)ids[s] * ROW_BYTES + sub * 32, v[s]);
    }

    // Max over this half-warp's 10 rows.
    float m[8];
#pragma unroll
    for (int j = 0; j < 8; ++j) m[j] = v[0][j];
#pragma unroll
    for (int s = 1; s < NUM_SAMPLE; ++s)
#pragma unroll
        for (int j = 0; j < 8; ++j) m[j] = fmaxf(m[j], v[s][j]);

    // Each half-warp stores its full 512B row: 16 lanes x 32B (2 x v4.cs).
    if (active) {
        char* dst = out + (size_t)q * ROW_BYTES + sub * 32;
        stg_streaming16(dst,      m[0], m[1], m[2], m[3]);
        stg_streaming16(dst + 16, m[4], m[5], m[6], m[7]);
    }
}

extern "C" void kernel_launch(void* const* d_in, const int* in_sizes, int n_in,
                              void* d_out, int out_size)
{
    const char* features = (const char*)d_in[0];
    const int*  nbrs     = (const int*)d_in[1];
    // d_in[2] is num_sample (device scalar) — shape is static, hardcoded to 10.

    const int num_query = in_sizes[1] / NUM_SAMPLE;   // 100'000

    const int warps_needed = (num_query + 1) / 2;     // 2 queries per warp
    const int warps_per_block = 4;                    // 128 threads
    const int blocks = (warps_needed + warps_per_block - 1) / warps_per_block;

    maxpool_agg_kernel<<<blocks, warps_per_block * 32>>>(
        features, nbrs, (char*)d_out, num_query);
}